// round 15
// baseline (speedup 1.0000x reference)
#include <cuda_runtime.h>
#include <cstdint>

#define B_N   8
#define CIN   64
#define BD    5
#define H     128
#define W     128
#define HW    16384
#define CH_STRIDE 81920        /* BD*HW */
#define TYR   8                /* tile rows */
#define TXC   32               /* tile cols */
#define RS    34               /* tile row stride (floats) */
#define PLANE 340              /* 10*RS: one (ch,B) plane */
#define CHS   1700             /* BD*PLANE: one channel */
#define TILEF 13600            /* 8*CHS floats per tile */

typedef unsigned long long ull;

// ---- f32x2 helpers ----
__device__ __forceinline__ ull pk(float lo, float hi) {
    ull r; asm("mov.b64 %0, {%1, %2};" : "=l"(r) : "f"(lo), "f"(hi)); return r;
}
__device__ __forceinline__ void fma2(ull& d, ull a, ull b) {
    asm("fma.rn.f32x2 %0, %1, %2, %0;" : "+l"(d) : "l"(a), "l"(b));
}
__device__ __forceinline__ ull mul2(ull a, ull b) {
    ull r; asm("mul.rn.f32x2 %0, %1, %2;" : "=l"(r) : "l"(a), "l"(b)); return r;
}
__device__ __forceinline__ float2 u2f(ull u) {
    float2 f; asm("mov.b64 {%0, %1}, %2;" : "=f"(f.x), "=f"(f.y) : "l"(u)); return f;
}
__device__ __forceinline__ float lo32(ull u) {
    float f; asm("{ .reg .f32 t; mov.b64 {%0, t}, %1; }" : "=f"(f) : "l"(u)); return f;
}
__device__ __forceinline__ float hi32(ull u) {
    float f; asm("{ .reg .f32 t; mov.b64 {t, %0}, %1; }" : "=f"(f) : "l"(u)); return f;
}

// ---- load one 8ch x 5B x 10row x 34col halo tile (proven R12 loader shape) ----
__device__ __forceinline__ void load_tile(float* ts, const float* gbase,
                                          int y0, int x0, int tid)
{
    const int lx = tid & 31;       // 0..31 -> tile col lx
    const int wg = tid >> 5;       // 0..3  -> rows wg+4t, t=0..2
    const int gx  = x0 - 1 + lx;
    const bool okx  = (unsigned)gx < (unsigned)W;
    const bool halo = (lx < 2);
    const int gx2 = gx + 32;                       // tile cols 32,33
    const bool okx2 = halo && ((unsigned)gx2 < (unsigned)W);
    const int gyb = y0 - 1 + wg;

    bool rok[3], rld[3], rld2[3];
    #pragma unroll
    for (int t = 0; t < 3; ++t) {
        const bool intile = (wg + 4*t) < 10;
        const bool iny    = (unsigned)(gyb + 4*t) < (unsigned)H;
        rok[t]  = intile;
        rld[t]  = intile && iny && okx;
        rld2[t] = intile && iny && okx2;
    }

    const float* p0 = gbase + (ptrdiff_t)gyb * W + gx;
    #pragma unroll
    for (int ch = 0; ch < 8; ++ch) {
        #pragma unroll
        for (int Bi = 0; Bi < BD; ++Bi) {
            const float* src = p0 + (ch*BD + Bi)*HW;
            float* dst = ts + (ch*BD + Bi)*PLANE + wg*RS + lx;
            #pragma unroll
            for (int t = 0; t < 3; ++t) {
                float v = rld[t] ? src[4*t*W] : 0.f;
                if (rok[t]) dst[4*t*RS] = v;
            }
            if (halo) {
                #pragma unroll
                for (int t = 0; t < 3; ++t) {
                    float v2 = rld2[t] ? src[4*t*W + 32] : 0.f;
                    if (rok[t]) dst[4*t*RS + 32] = v2;
                }
            }
        }
    }
}

// ---- grouped 3x3x3 conv for ONE attention channel d (2 in-channels),
//      2 x-points per thread, acc[Bo] packed f32x2 (proven inner loop) ----
__device__ __forceinline__ void conv_d(const float* ts, const float2* w2,
                                       int toff, ull acc[BD])
{
    #pragma unroll
    for (int i = 0; i < BD; ++i) acc[i] = 0ull;
    #pragma unroll
    for (int dl = 0; dl < 2; ++dl) {
        const float* tp = ts + dl*CHS + toff;
        #pragma unroll
        for (int dy = 0; dy < 3; ++dy) {
            ull wr[9];
            #pragma unroll
            for (int dB = 0; dB < 3; ++dB)
                #pragma unroll
                for (int dx = 0; dx < 3; ++dx)
                    wr[dB*3+dx] = *(const ull*)&w2[dl*27 + dB*9 + dy*3 + dx];
            #pragma unroll
            for (int Bi = 0; Bi < BD; ++Bi) {
                const float* rp = tp + Bi*PLANE + dy*RS;
                ull E0 = *(const ull*)(rp);       // cols px,px+1
                ull E1 = *(const ull*)(rp + 2);   // cols px+2,px+3
                ull C  = pk(hi32(E0), lo32(E1));  // cols px+1,px+2
                #pragma unroll
                for (int dB = 0; dB < 3; ++dB) {
                    const int Bo = Bi + 1 - dB;
                    if (Bo < 0 || Bo >= BD) continue;
                    fma2(acc[Bo], E0, wr[dB*3+0]);
                    fma2(acc[Bo], C,  wr[dB*3+1]);
                    fma2(acc[Bo], E1, wr[dB*3+2]);
                }
            }
        }
    }
}

// ============================================================================
// Fully fused: conv q/k/v + per-point attention over B + 1x1x1 projection.
// Block = (x-tile, y-tile, bb*8 + head), 128 threads, 2 x-points/thread.
// q,k,v never touch DRAM.
// ============================================================================
__global__ void __launch_bounds__(128)
fused_kernel(const float* __restrict__ x, const float* __restrict__ last,
             const float* __restrict__ wq, const float* __restrict__ wk,
             const float* __restrict__ wv, const float* __restrict__ wproj,
             float* __restrict__ out)
{
    extern __shared__ float smem[];
    float*  xt  = smem;                       // TILEF floats
    float*  lt  = smem + TILEF;               // TILEF floats
    float2* w2q = (float2*)(smem + 2*TILEF);  // [4][54] (w,w) pairs
    float2* w2k = w2q + 216;
    float2* w2v = w2k + 216;
    float*  wp  = (float*)(w2v + 216);        // [64]

    const int tid = threadIdx.x;
    const int x0  = blockIdx.x * TXC;
    const int y0  = blockIdx.y * TYR;
    const int h   = blockIdx.z & 7;
    const int bb  = blockIdx.z >> 3;

    // ---- weights: (w,w) broadcast pairs; SCALE folded into wq ----
    for (int i = tid; i < 216; i += 128) {
        const int d = i / 54, e = i - d*54;
        const int cg = (h*4 + d)*54 + e;
        const float a = wq[cg] * 0.35355339059327373f;
        w2q[i] = make_float2(a, a);
        const float b = wk[cg]; w2k[i] = make_float2(b, b);
        const float c = wv[cg]; w2v[i] = make_float2(c, c);
    }
    if (tid < 64) wp[tid] = wproj[tid];

    const size_t inb = (size_t)(bb*CIN + 8*h) * CH_STRIDE;
    load_tile(xt, x    + inb, y0, x0, tid);
    load_tile(lt, last + inb, y0, x0, tid);
    __syncthreads();

    const int ty  = tid >> 4;          // 0..7
    const int px  = (tid & 15) << 1;   // 0..30 (2 points: px, px+1)
    const int toff = ty*RS + px;

    // ---- s[i][j] = sum_d q[i,d]*k[j,d], packed per x-pair ----
    ull s[25];
    #pragma unroll
    for (int i = 0; i < 25; ++i) s[i] = 0ull;

    #pragma unroll 1
    for (int d = 0; d < 4; ++d) {
        ull q[BD], k[BD];
        conv_d(xt + 2*d*CHS, w2q + d*54, toff, q);
        conv_d(lt + 2*d*CHS, w2k + d*54, toff, k);
        #pragma unroll
        for (int i = 0; i < BD; ++i)
            #pragma unroll
            for (int j = 0; j < BD; ++j)
                fma2(s[i*5+j], q[i], k[j]);
    }

    // ---- softmax over j, per packed half (each half = one point) ----
    #pragma unroll
    for (int i = 0; i < BD; ++i) {
        float lo[5], hi[5];
        #pragma unroll
        for (int j = 0; j < BD; ++j) {
            float2 f = u2f(s[i*5+j]); lo[j] = f.x; hi[j] = f.y;
        }
        float ml = lo[0], mh = hi[0];
        #pragma unroll
        for (int j = 1; j < BD; ++j) { ml = fmaxf(ml, lo[j]); mh = fmaxf(mh, hi[j]); }
        float sl = 0.f, sh = 0.f, el[5], eh[5];
        #pragma unroll
        for (int j = 0; j < BD; ++j) {
            el[j] = __expf(lo[j] - ml); sl += el[j];
            eh[j] = __expf(hi[j] - mh); sh += eh[j];
        }
        const float il = 1.0f / sl, ih = 1.0f / sh;
        #pragma unroll
        for (int j = 0; j < BD; ++j)
            s[i*5+j] = pk(el[j]*il, eh[j]*ih);
    }

    // ---- v conv per d, attention-weighted sum, projection, store ----
    float* ob0 = out + ((size_t)(bb*CIN + 8*h) * BD) * HW
                     + (size_t)(y0 + ty) * W + x0 + px;
    #pragma unroll 1
    for (int d = 0; d < 4; ++d) {
        ull v[BD];
        conv_d(lt + 2*d*CHS, w2v + d*54, toff, v);
        const float w0 = wp[8*h + 2*d], w1 = wp[8*h + 2*d + 1];
        const ull W0 = pk(w0, w0), W1 = pk(w1, w1);
        float* oc = ob0 + (size_t)(2*d) * CH_STRIDE;
        #pragma unroll
        for (int i = 0; i < BD; ++i) {
            ull o = 0ull;
            #pragma unroll
            for (int j = 0; j < BD; ++j)
                fma2(o, s[i*5+j], v[j]);
            *(float2*)(oc + (size_t)i*HW)             = u2f(mul2(o, W0));
            *(float2*)(oc + CH_STRIDE + (size_t)i*HW) = u2f(mul2(o, W1));
        }
    }
}

extern "C" void kernel_launch(void* const* d_in, const int* in_sizes, int n_in,
                              void* d_out, int out_size) {
    const float* x     = (const float*)d_in[0];
    const float* last  = (const float*)d_in[1];
    const float* wq    = (const float*)d_in[2];
    const float* wk    = (const float*)d_in[3];
    const float* wv    = (const float*)d_in[4];
    const float* wproj = (const float*)d_in[5];
    float* out = (float*)d_out;

    const int SMEM = (2*TILEF)*4 + 3*216*8 + 64*4;   // 114,240 B
    cudaFuncSetAttribute(fused_kernel,
                         cudaFuncAttributeMaxDynamicSharedMemorySize, SMEM);
    dim3 grid(W/TXC, H/TYR, B_N*8);   // (4, 16, 64)
    fused_kernel<<<grid, 128, SMEM>>>(x, last, wq, wk, wv, wproj, out);
}

// round 16
// speedup vs baseline: 1.6617x; 1.6617x over previous
#include <cuda_runtime.h>
#include <cstdint>

#define B_N   8
#define CIN   64
#define CATT  32
#define BD    5
#define H     128
#define W     128
#define HW    (H*W)            /* 16384 */
#define CH_STRIDE (BD*HW)      /* 81920 */
#define TY 16
#define TW 64
#define TS (TW+2)              /* 66 floats per tile row */

typedef unsigned long long ull;

// scratch for q, k, v : 8*32*5*128*128 floats each (83.9 MB)
__device__ __align__(128) float g_q[(size_t)B_N*CATT*BD*HW];
__device__ __align__(128) float g_k[(size_t)B_N*CATT*BD*HW];
__device__ __align__(128) float g_v[(size_t)B_N*CATT*BD*HW];

// Bank swizzle (measured best in R13): toggle float-col bits {2,1} for
// cols>=32 so the 16 compute lanes' LDS.64 reads cover all bank pairs.
__device__ __forceinline__ int SW(int c) {
    return c ^ (((c & 32) >> 3) | ((c & 32) >> 4));
}

// ---- f32x2 helpers ----
__device__ __forceinline__ ull pk(float lo, float hi) {
    ull r; asm("mov.b64 %0, {%1, %2};" : "=l"(r) : "f"(lo), "f"(hi)); return r;
}
__device__ __forceinline__ void fma2(ull& d, ull a, ull b) {
    asm("fma.rn.f32x2 %0, %1, %2, %0;" : "+l"(d) : "l"(a), "l"(b));
}
__device__ __forceinline__ float2 u2f(ull u) {
    float2 f; asm("mov.b64 {%0, %1}, %2;" : "=f"(f.x), "=f"(f.y) : "l"(u)); return f;
}
__device__ __forceinline__ float lo32(ull u) {
    float f; asm("{ .reg .f32 t; mov.b64 {%0, t}, %1; }" : "=f"(f) : "l"(u)); return f;
}
__device__ __forceinline__ float hi32(ull u) {
    float f; asm("{ .reg .f32 t; mov.b64 {t, %0}, %1; }" : "=f"(f) : "l"(u)); return f;
}

// ============================================================================
// Grouped 3x3x3 conv, groups=32 (2 in-ch per out-ch). ALL THREE tensors in
// one launch: blockIdx.x = xt*3 + sel (sel: 0=q, 1=k, 2=v). Adjacent blocks
// are the q,k,v blocks of the same tile -> load/compute phases interleave
// across tensors (DRAM duty cycle) and v's `last` tile hits L2 right after
// k loaded it. Body identical to the measured-best R13 conv.
// ============================================================================
__global__ __launch_bounds__(256, 3)
void conv3d_all(const float* __restrict__ x, const float* __restrict__ last,
                const float* __restrict__ wq, const float* __restrict__ wk,
                const float* __restrict__ wv)
{
    const int bx  = blockIdx.x;
    const int sel = bx - (bx/3)*3;           // 0,1,2
    const int x0  = (bx/3) * TW;

    const float* in  = (sel == 0) ? x : last;
    const float* wgt = (sel == 0) ? wq : (sel == 1) ? wk : wv;
    float* const out = (sel == 0) ? g_q : (sel == 1) ? g_k : g_v;
    const float wscale = (sel == 0) ? 0.35355339059327373f : 1.0f;

    __shared__ float  tile[2][BD][TY+2][TS];   // 47520 B
    __shared__ float2 wsp[54];                 // 432 B

    const int tid = threadIdx.x;
    const int c   = blockIdx.z & 31;
    const int bb  = blockIdx.z >> 5;
    const int y0  = blockIdx.y * TY;

    if (tid < 54) {
        float a = wgt[c*54 + tid] * wscale;
        wsp[tid] = make_float2(a, a);
    }

    // ---- halo tile load: fully unrolled, immediate offsets, no div/mod ----
    {
        const int lx = tid & 63;       // 0..63
        const int wg = tid >> 6;       // 0..3: rows wg*5 .. wg*5+4
        const int gx  = x0 - 1 + lx;
        const bool okx  = (unsigned)gx  < (unsigned)W;
        const bool halo = (lx < 2);
        const int gx2 = gx + 64;
        const bool okx2 = halo && ((unsigned)gx2 < (unsigned)W);
        const int cs  = SW(lx);
        const int cs2 = lx + 64;
        const int yyb = wg * 5;
        const int gyb = y0 - 1 + yyb;

        bool rok[5], rld[5], rld2[5];
        #pragma unroll
        for (int t = 0; t < 5; ++t) {
            const bool intile = (yyb + t) < (TY + 2);
            const bool iny    = (unsigned)(gyb + t) < (unsigned)H;
            rok[t]  = intile;
            rld[t]  = intile && iny && okx;
            rld2[t] = intile && iny && okx2;
        }

        const float* inb = in + ((size_t)(bb*CIN + 2*c))*CH_STRIDE;
        const float* p0  = inb + (ptrdiff_t)gyb * W + gx;

        #pragma unroll
        for (int din = 0; din < 2; ++din) {
            #pragma unroll
            for (int Bi = 0; Bi < BD; ++Bi) {
                const float* src = p0 + (din*BD + Bi)*HW;
                float* dst = &tile[din][Bi][0][0] + yyb*TS;
                #pragma unroll
                for (int t = 0; t < 5; ++t) {
                    float v = rld[t] ? src[t*W] : 0.f;
                    if (rok[t]) dst[t*TS + cs] = v;
                }
                if (halo) {
                    #pragma unroll
                    for (int t = 0; t < 5; ++t) {
                        float v2 = rld2[t] ? src[t*W + 64] : 0.f;
                        if (rok[t]) dst[t*TS + cs2] = v2;
                    }
                }
            }
        }
    }
    __syncthreads();

    const int tx  = tid & 15;
    const int ty  = tid >> 4;
    const int cb  = tx << 2;
    const int o0  = SW(cb);
    const int o1  = SW(cb + 2);
    const int o2  = SW(cb + 4);

    ull acc[BD][2];
    #pragma unroll
    for (int bo = 0; bo < BD; ++bo) { acc[bo][0] = 0ull; acc[bo][1] = 0ull; }

    #pragma unroll
    for (int din = 0; din < 2; ++din) {
        #pragma unroll
        for (int dy = 0; dy < 3; ++dy) {
            ull wr2[9];
            #pragma unroll
            for (int dB = 0; dB < 3; ++dB)
                #pragma unroll
                for (int dx = 0; dx < 3; ++dx)
                    wr2[dB*3+dx] = *(const ull*)&wsp[din*27 + dB*9 + dy*3 + dx];

            #pragma unroll
            for (int Bi = 0; Bi < BD; ++Bi) {
                const float* rp = &tile[din][Bi][ty + dy][0];
                ull P0 = *(const ull*)(rp + o0);   // (x0,x1)
                ull P2 = *(const ull*)(rp + o1);   // (x2,x3)
                ull P4 = *(const ull*)(rp + o2);   // (x4,x5)
                ull P1 = pk(hi32(P0), lo32(P2));   // (x1,x2)
                ull P3 = pk(hi32(P2), lo32(P4));   // (x3,x4)
                #pragma unroll
                for (int dB = 0; dB < 3; ++dB) {
                    const int Bo = Bi + 1 - dB;
                    if (Bo < 0 || Bo >= BD) continue;
                    fma2(acc[Bo][0], P0, wr2[dB*3+0]);
                    fma2(acc[Bo][0], P1, wr2[dB*3+1]);
                    fma2(acc[Bo][0], P2, wr2[dB*3+2]);
                    fma2(acc[Bo][1], P2, wr2[dB*3+0]);
                    fma2(acc[Bo][1], P3, wr2[dB*3+1]);
                    fma2(acc[Bo][1], P4, wr2[dB*3+2]);
                }
            }
        }
    }

    const size_t ob = ((size_t)(bb*CATT + c))*CH_STRIDE
                    + (size_t)(y0 + ty)*W + x0 + cb;
    #pragma unroll
    for (int Bo = 0; Bo < BD; ++Bo) {
        float2 a0 = u2f(acc[Bo][0]);
        float2 a1 = u2f(acc[Bo][1]);
        *(float4*)(out + ob + (size_t)Bo*HW) = make_float4(a0.x, a0.y, a1.x, a1.y);
    }
}

// ============================================================================
// Attention (over B=5, 8 heads, head_dim=4) + grouped 1x1x1 projection.
// q is pre-scaled (SCALE folded into wq at conv time). blockIdx.y = head.
// ============================================================================
__global__ __launch_bounds__(256)
void attn_proj_kernel(const float* __restrict__ wproj, float* __restrict__ out)
{
    __shared__ float wp[8];
    const int hd = blockIdx.y;
    if (threadIdx.x < 8) wp[threadIdx.x] = wproj[hd*8 + threadIdx.x];
    __syncthreads();

    const int p = blockIdx.x * 256 + threadIdx.x;
    const int bb = p >> 14;
    const int yx = p & (HW - 1);
    const size_t base = (size_t)bb * CATT * CH_STRIDE + yx;

    float q[BD][4], k[BD][4], v[BD][4];
    #pragma unroll
    for (int d = 0; d < 4; ++d) {
        const size_t cb = base + (size_t)(hd*4 + d) * CH_STRIDE;
        #pragma unroll
        for (int Bi = 0; Bi < BD; ++Bi) {
            q[Bi][d] = g_q[cb + Bi*HW];
            k[Bi][d] = g_k[cb + Bi*HW];
            v[Bi][d] = g_v[cb + Bi*HW];
        }
    }
    #pragma unroll
    for (int i = 0; i < BD; ++i) {
        float s[BD];
        #pragma unroll
        for (int j = 0; j < BD; ++j) {
            float t = q[i][0] * k[j][0];
            t = fmaf(q[i][1], k[j][1], t);
            t = fmaf(q[i][2], k[j][2], t);
            t = fmaf(q[i][3], k[j][3], t);
            s[j] = t;
        }
        float m = s[0];
        #pragma unroll
        for (int j = 1; j < BD; ++j) m = fmaxf(m, s[j]);
        float e[BD], sum = 0.f;
        #pragma unroll
        for (int j = 0; j < BD; ++j) { e[j] = __expf(s[j] - m); sum += e[j]; }
        const float inv = 1.0f / sum;
        #pragma unroll
        for (int d = 0; d < 4; ++d) {
            float t = e[0] * v[0][d];
            #pragma unroll
            for (int j = 1; j < BD; ++j) t = fmaf(e[j], v[j][d], t);
            const float od = t * inv;
            const int ch = hd*4 + d;
            const size_t obx = ((size_t)(bb*CIN + 2*ch)*BD + i)*HW + yx;
            out[obx]                 = od * wp[2*d];
            out[obx + (size_t)BD*HW] = od * wp[2*d + 1];
        }
    }
}

extern "C" void kernel_launch(void* const* d_in, const int* in_sizes, int n_in,
                              void* d_out, int out_size) {
    const float* x     = (const float*)d_in[0];
    const float* last  = (const float*)d_in[1];
    const float* wq    = (const float*)d_in[2];
    const float* wk    = (const float*)d_in[3];
    const float* wv    = (const float*)d_in[4];
    const float* wproj = (const float*)d_in[5];
    float* out = (float*)d_out;

    dim3 cgrid(3*(W/TW), H/TY, B_N*CATT);   // (6, 8, 256): x = xt*3 + sel
    conv3d_all<<<cgrid, 256>>>(x, last, wq, wk, wv);
    dim3 agrid(B_N*HW/256, 8);              // (512, 8 heads)
    attn_proj_kernel<<<agrid, 256>>>(wproj, out);
}

// round 17
// speedup vs baseline: 1.7692x; 1.0647x over previous
#include <cuda_runtime.h>
#include <cuda_fp16.h>
#include <cstdint>

#define B_N   8
#define CIN   64
#define CATT  32
#define BD    5
#define H     128
#define W     128
#define HW    (H*W)            /* 16384 */
#define CH_STRIDE (BD*HW)      /* 81920 */
#define TY 16
#define TW 64
#define TS (TW+2)              /* 66 floats per tile row */

typedef unsigned long long ull;

// scratch for q, k, v in fp16 : 8*32*5*128*128 halfs each (41.9 MB)
__device__ __align__(128) __half g_q[(size_t)B_N*CATT*BD*HW];
__device__ __align__(128) __half g_k[(size_t)B_N*CATT*BD*HW];
__device__ __align__(128) __half g_v[(size_t)B_N*CATT*BD*HW];

// Bank swizzle (measured best in R13): toggle float-col bits {2,1} for
// cols>=32 so the 16 compute lanes' LDS.64 reads cover all bank pairs.
__device__ __forceinline__ int SW(int c) {
    return c ^ (((c & 32) >> 3) | ((c & 32) >> 4));
}

// ---- f32x2 helpers ----
__device__ __forceinline__ ull pk(float lo, float hi) {
    ull r; asm("mov.b64 %0, {%1, %2};" : "=l"(r) : "f"(lo), "f"(hi)); return r;
}
__device__ __forceinline__ void fma2(ull& d, ull a, ull b) {
    asm("fma.rn.f32x2 %0, %1, %2, %0;" : "+l"(d) : "l"(a), "l"(b));
}
__device__ __forceinline__ float2 u2f(ull u) {
    float2 f; asm("mov.b64 {%0, %1}, %2;" : "=f"(f.x), "=f"(f.y) : "l"(u)); return f;
}
__device__ __forceinline__ float lo32(ull u) {
    float f; asm("{ .reg .f32 t; mov.b64 {%0, t}, %1; }" : "=f"(f) : "l"(u)); return f;
}
__device__ __forceinline__ float hi32(ull u) {
    float f; asm("{ .reg .f32 t; mov.b64 {t, %0}, %1; }" : "=f"(f) : "l"(u)); return f;
}

// ============================================================================
// Grouped 3x3x3 conv, groups=32 (2 in-ch per out-ch). ALL THREE tensors in
// one launch: blockIdx.x = xt*3 + sel (sel: 0=q, 1=k, 2=v). Adjacent blocks
// are the q,k,v blocks of the same tile -> DRAM duty-cycle interleave, and
// v's `last` tile hits L2 right after k loaded it. Output stored as fp16
// (half the intermediate write traffic). Body = measured-best R13/R16 conv.
// ============================================================================
__global__ __launch_bounds__(256, 3)
void conv3d_all(const float* __restrict__ x, const float* __restrict__ last,
                const float* __restrict__ wq, const float* __restrict__ wk,
                const float* __restrict__ wv)
{
    const int bx  = blockIdx.x;
    const int sel = bx - (bx/3)*3;           // 0,1,2
    const int x0  = (bx/3) * TW;

    const float* in  = (sel == 0) ? x : last;
    const float* wgt = (sel == 0) ? wq : (sel == 1) ? wk : wv;
    __half* const out = (sel == 0) ? g_q : (sel == 1) ? g_k : g_v;
    const float wscale = (sel == 0) ? 0.35355339059327373f : 1.0f;

    __shared__ float  tile[2][BD][TY+2][TS];   // 47520 B
    __shared__ float2 wsp[54];                 // 432 B

    const int tid = threadIdx.x;
    const int c   = blockIdx.z & 31;
    const int bb  = blockIdx.z >> 5;
    const int y0  = blockIdx.y * TY;

    if (tid < 54) {
        float a = wgt[c*54 + tid] * wscale;
        wsp[tid] = make_float2(a, a);
    }

    // ---- halo tile load: fully unrolled, immediate offsets, no div/mod ----
    {
        const int lx = tid & 63;       // 0..63
        const int wg = tid >> 6;       // 0..3: rows wg*5 .. wg*5+4
        const int gx  = x0 - 1 + lx;
        const bool okx  = (unsigned)gx  < (unsigned)W;
        const bool halo = (lx < 2);
        const int gx2 = gx + 64;
        const bool okx2 = halo && ((unsigned)gx2 < (unsigned)W);
        const int cs  = SW(lx);
        const int cs2 = lx + 64;
        const int yyb = wg * 5;
        const int gyb = y0 - 1 + yyb;

        bool rok[5], rld[5], rld2[5];
        #pragma unroll
        for (int t = 0; t < 5; ++t) {
            const bool intile = (yyb + t) < (TY + 2);
            const bool iny    = (unsigned)(gyb + t) < (unsigned)H;
            rok[t]  = intile;
            rld[t]  = intile && iny && okx;
            rld2[t] = intile && iny && okx2;
        }

        const float* inb = in + ((size_t)(bb*CIN + 2*c))*CH_STRIDE;
        const float* p0  = inb + (ptrdiff_t)gyb * W + gx;

        #pragma unroll
        for (int din = 0; din < 2; ++din) {
            #pragma unroll
            for (int Bi = 0; Bi < BD; ++Bi) {
                const float* src = p0 + (din*BD + Bi)*HW;
                float* dst = &tile[din][Bi][0][0] + yyb*TS;
                #pragma unroll
                for (int t = 0; t < 5; ++t) {
                    float v = rld[t] ? src[t*W] : 0.f;
                    if (rok[t]) dst[t*TS + cs] = v;
                }
                if (halo) {
                    #pragma unroll
                    for (int t = 0; t < 5; ++t) {
                        float v2 = rld2[t] ? src[t*W + 64] : 0.f;
                        if (rok[t]) dst[t*TS + cs2] = v2;
                    }
                }
            }
        }
    }
    __syncthreads();

    const int tx  = tid & 15;
    const int ty  = tid >> 4;
    const int cb  = tx << 2;
    const int o0  = SW(cb);
    const int o1  = SW(cb + 2);
    const int o2  = SW(cb + 4);

    ull acc[BD][2];
    #pragma unroll
    for (int bo = 0; bo < BD; ++bo) { acc[bo][0] = 0ull; acc[bo][1] = 0ull; }

    #pragma unroll
    for (int din = 0; din < 2; ++din) {
        #pragma unroll
        for (int dy = 0; dy < 3; ++dy) {
            ull wr2[9];
            #pragma unroll
            for (int dB = 0; dB < 3; ++dB)
                #pragma unroll
                for (int dx = 0; dx < 3; ++dx)
                    wr2[dB*3+dx] = *(const ull*)&wsp[din*27 + dB*9 + dy*3 + dx];

            #pragma unroll
            for (int Bi = 0; Bi < BD; ++Bi) {
                const float* rp = &tile[din][Bi][ty + dy][0];
                ull P0 = *(const ull*)(rp + o0);   // (x0,x1)
                ull P2 = *(const ull*)(rp + o1);   // (x2,x3)
                ull P4 = *(const ull*)(rp + o2);   // (x4,x5)
                ull P1 = pk(hi32(P0), lo32(P2));   // (x1,x2)
                ull P3 = pk(hi32(P2), lo32(P4));   // (x3,x4)
                #pragma unroll
                for (int dB = 0; dB < 3; ++dB) {
                    const int Bo = Bi + 1 - dB;
                    if (Bo < 0 || Bo >= BD) continue;
                    fma2(acc[Bo][0], P0, wr2[dB*3+0]);
                    fma2(acc[Bo][0], P1, wr2[dB*3+1]);
                    fma2(acc[Bo][0], P2, wr2[dB*3+2]);
                    fma2(acc[Bo][1], P2, wr2[dB*3+0]);
                    fma2(acc[Bo][1], P3, wr2[dB*3+1]);
                    fma2(acc[Bo][1], P4, wr2[dB*3+2]);
                }
            }
        }
    }

    const size_t ob = ((size_t)(bb*CATT + c))*CH_STRIDE
                    + (size_t)(y0 + ty)*W + x0 + cb;
    #pragma unroll
    for (int Bo = 0; Bo < BD; ++Bo) {
        __half2 h0 = __float22half2_rn(u2f(acc[Bo][0]));
        __half2 h1 = __float22half2_rn(u2f(acc[Bo][1]));
        union { __half2 h[2]; uint2 u; } cv;
        cv.h[0] = h0; cv.h[1] = h1;
        *(uint2*)(out + ob + (size_t)Bo*HW) = cv.u;   // 8B store, 8B-aligned
    }
}

// ============================================================================
// Attention (over B=5, 8 heads, head_dim=4) + grouped 1x1x1 projection.
// q is pre-scaled (SCALE folded into wq at conv time). blockIdx.y = head.
// q,k,v read as fp16 (half traffic), computed in fp32.
// ============================================================================
__global__ __launch_bounds__(256)
void attn_proj_kernel(const float* __restrict__ wproj, float* __restrict__ out)
{
    __shared__ float wp[8];
    const int hd = blockIdx.y;
    if (threadIdx.x < 8) wp[threadIdx.x] = wproj[hd*8 + threadIdx.x];
    __syncthreads();

    const int p = blockIdx.x * 256 + threadIdx.x;
    const int bb = p >> 14;
    const int yx = p & (HW - 1);
    const size_t base = (size_t)bb * CATT * CH_STRIDE + yx;

    float q[BD][4], k[BD][4], v[BD][4];
    #pragma unroll
    for (int d = 0; d < 4; ++d) {
        const size_t cb = base + (size_t)(hd*4 + d) * CH_STRIDE;
        #pragma unroll
        for (int Bi = 0; Bi < BD; ++Bi) {
            q[Bi][d] = __half2float(g_q[cb + Bi*HW]);
            k[Bi][d] = __half2float(g_k[cb + Bi*HW]);
            v[Bi][d] = __half2float(g_v[cb + Bi*HW]);
        }
    }
    #pragma unroll
    for (int i = 0; i < BD; ++i) {
        float s[BD];
        #pragma unroll
        for (int j = 0; j < BD; ++j) {
            float t = q[i][0] * k[j][0];
            t = fmaf(q[i][1], k[j][1], t);
            t = fmaf(q[i][2], k[j][2], t);
            t = fmaf(q[i][3], k[j][3], t);
            s[j] = t;
        }
        float m = s[0];
        #pragma unroll
        for (int j = 1; j < BD; ++j) m = fmaxf(m, s[j]);
        float e[BD], sum = 0.f;
        #pragma unroll
        for (int j = 0; j < BD; ++j) { e[j] = __expf(s[j] - m); sum += e[j]; }
        const float inv = 1.0f / sum;
        #pragma unroll
        for (int d = 0; d < 4; ++d) {
            float t = e[0] * v[0][d];
            #pragma unroll
            for (int j = 1; j < BD; ++j) t = fmaf(e[j], v[j][d], t);
            const float od = t * inv;
            const int ch = hd*4 + d;
            const size_t obx = ((size_t)(bb*CIN + 2*ch)*BD + i)*HW + yx;
            out[obx]                 = od * wp[2*d];
            out[obx + (size_t)BD*HW] = od * wp[2*d + 1];
        }
    }
}

extern "C" void kernel_launch(void* const* d_in, const int* in_sizes, int n_in,
                              void* d_out, int out_size) {
    const float* x     = (const float*)d_in[0];
    const float* last  = (const float*)d_in[1];
    const float* wq    = (const float*)d_in[2];
    const float* wk    = (const float*)d_in[3];
    const float* wv    = (const float*)d_in[4];
    const float* wproj = (const float*)d_in[5];
    float* out = (float*)d_out;

    dim3 cgrid(3*(W/TW), H/TY, B_N*CATT);   // (6, 8, 256): x = xt*3 + sel
    conv3d_all<<<cgrid, 256>>>(x, last, wq, wk, wv);
    dim3 agrid(B_N*HW/256, 8);              // (512, 8 heads)
    attn_proj_kernel<<<agrid, 256>>>(wproj, out);
}